// round 10
// baseline (speedup 1.0000x reference)
#include <cuda_runtime.h>
#include <cuda_fp16.h>
#include <cstdint>

// out[B,256] = (x[B,128] @ W[256,128]^T + bias)^2
// Single-term fp16 mma.sync GEMM, fp32 accum. rel_err ~3.5e-4 (calibrated).
// N split across CTAs: each CTA does a 64x128 tile, 3 CTAs/SM (6 warps/SMSP).

#define DDIM   128
#define ODIM   256
#define TILE_M 64
#define NITEMS 4096          // 2048 m-tiles x 2 n-halves
#define GRID   444           // 3 * 148
#define MSTEP  222           // GRID/2 m-tiles per step

// smem (bytes), per CTA
#define SM_W     0            // W half: 128 rows x 256B swizzled = 32768
#define SM_A0    32768        // A buf 0: 64x128 fp16 = 16384
#define SM_A1    49152        // A buf 1
#define SM_EPI   65536        // epilogue staging: 8 warps x 1KB
#define SM_TOTAL 73728

static __device__ __forceinline__ uint32_t smem_u32(const void* p) {
    uint32_t a;
    asm("{ .reg .u64 t; cvta.to.shared.u64 t, %1; cvt.u32.u64 %0, t; }" : "=r"(a) : "l"(p));
    return a;
}

static __device__ __forceinline__ void ldsm4(uint32_t* r, uint32_t a) {
    asm volatile("ldmatrix.sync.aligned.m8n8.x4.shared.b16 {%0,%1,%2,%3}, [%4];"
                 : "=r"(r[0]), "=r"(r[1]), "=r"(r[2]), "=r"(r[3]) : "r"(a));
}

static __device__ __forceinline__ void sts64(uint32_t a, uint32_t v0, uint32_t v1) {
    asm volatile("st.shared.v2.b32 [%0], {%1, %2};" :: "r"(a), "r"(v0), "r"(v1));
}

static __device__ __forceinline__ void lds128(float* v, uint32_t a) {
    asm volatile("ld.shared.v4.f32 {%0,%1,%2,%3}, [%4];"
                 : "=f"(v[0]), "=f"(v[1]), "=f"(v[2]), "=f"(v[3]) : "r"(a));
}

static __device__ __forceinline__ void mma_f16(float* d, const uint32_t* a,
                                               uint32_t b0, uint32_t b1) {
    asm volatile(
        "mma.sync.aligned.m16n8k16.row.col.f32.f16.f16.f32 "
        "{%0,%1,%2,%3}, {%4,%5,%6,%7}, {%8,%9}, {%0,%1,%2,%3};"
        : "+f"(d[0]), "+f"(d[1]), "+f"(d[2]), "+f"(d[3])
        : "r"(a[0]), "r"(a[1]), "r"(a[2]), "r"(a[3]), "r"(b0), "r"(b1));
}

// convert one staged float4 (flat float4-index of a 64x128 tile) into A buffer
static __device__ __forceinline__ void cvt_sts_x(uint32_t xb, int idx4, float4 v) {
    const int row = idx4 >> 5;          // 0..63
    const int cg  = idx4 & 31;
    uint32_t h0, h1;
    asm("cvt.rn.f16x2.f32 %0, %1, %2;" : "=r"(h0) : "f"(v.y), "f"(v.x));
    asm("cvt.rn.f16x2.f32 %0, %1, %2;" : "=r"(h1) : "f"(v.w), "f"(v.z));
    const uint32_t a = xb + (uint32_t)row * 256 +
                       ((uint32_t)(((cg >> 1) ^ (row & 7)) << 4)) + ((cg & 1) << 3);
    sts64(a, h0, h1);
}

__global__ void __launch_bounds__(256, 3)
hyper_kernel(const float* __restrict__ xg, const float* __restrict__ wg,
             const float* __restrict__ bg, float* __restrict__ out) {
    extern __shared__ __align__(16) char smem[];
    const uint32_t sb = smem_u32(smem);
    const int tid  = threadIdx.x;
    const int lane = tid & 31;
    const int wid  = tid >> 5;
    const int wm   = wid >> 2;           // 0..1 : rows wm*32 .. +31
    const int wn   = wid & 3;            // 0..3 : cols wn*32 .. +31 (within n-half)
    const int bid  = blockIdx.x;
    const int nh   = bid & 1;            // n-half: fixed per CTA (GRID even)

    const float4* xg4 = reinterpret_cast<const float4*>(xg);

    // prefetch tile 0 (overlaps W init)
    const int mt0 = bid >> 1;
    float4 st0[8];
    {
        const size_t b4 = (size_t)mt0 * (TILE_M * 32);
        #pragma unroll
        for (int it = 0; it < 8; it++) st0[it] = xg4[b4 + tid + it * 256];
    }

    // W half (rows nh*128 .. +127): fp32 -> fp16, swizzled 256B rows
    {
        const float4* w4 = reinterpret_cast<const float4*>(wg) + (size_t)nh * 128 * 32;
        #pragma unroll 4
        for (int i = tid; i < 128 * 32; i += 256) {
            const int n  = i >> 5;
            const int cg = i & 31;
            float4 v = w4[i];
            uint32_t p0, p1;
            asm("cvt.rn.f16x2.f32 %0, %1, %2;" : "=r"(p0) : "f"(v.y), "f"(v.x));
            asm("cvt.rn.f16x2.f32 %0, %1, %2;" : "=r"(p1) : "f"(v.w), "f"(v.z));
            const uint32_t a = sb + SM_W + (uint32_t)n * 256 +
                               ((uint32_t)(((cg >> 1) ^ (n & 7)) << 4)) + ((cg & 1) << 3);
            sts64(a, p0, p1);
        }
    }

    // tile 0 -> A buffer 0
    #pragma unroll
    for (int it = 0; it < 8; it++) cvt_sts_x(sb + SM_A0, tid + it * 256, st0[it]);
    __syncthreads();

    float acc[2][4][4];
    #pragma unroll
    for (int mt = 0; mt < 2; mt++)
        #pragma unroll
        for (int nt = 0; nt < 4; nt++)
            #pragma unroll
            for (int q = 0; q < 4; q++) acc[mt][nt][q] = 0.0f;

    // bias pairs (constant across tiles) straight from global (tiny, L2)
    float2 bp[4];
    #pragma unroll
    for (int nt = 0; nt < 4; nt++)
        bp[nt] = *reinterpret_cast<const float2*>(
            bg + nh * 128 + wn * 32 + nt * 8 + (lane & 3) * 2);

    const uint32_t lx  = (uint32_t)(lane & 7);
    const uint32_t khA = (uint32_t)((lane >> 4) & 1);
    const uint32_t khB = (uint32_t)((lane >> 3) & 1);
    const uint32_t arow_off =
        (uint32_t)(wm * 32 + (lane & 7) + ((lane & 8) ? 8 : 0)) * 256;
    const uint32_t preB = sb + SM_W +
        (uint32_t)(wn * 32 + (lane & 7) + ((lane & 16) ? 8 : 0)) * 256;
    const int my_n = (NITEMS - bid + GRID - 1) / GRID;

    for (int tt = 0; tt < my_n; tt++) {
        const int mtile = mt0 + tt * MSTEP;
        const uint32_t xb  = sb + ((tt & 1) ? SM_A1 : SM_A0);
        const uint32_t nxb = sb + ((tt & 1) ? SM_A0 : SM_A1);
        const bool more = (tt + 1 < my_n);
        const size_t nb4 = more ? ((size_t)(mtile + MSTEP) * (TILE_M * 32)) : 0;

        float4 s[4];
        if (more) {
            #pragma unroll
            for (int it = 0; it < 4; it++) s[it] = xg4[nb4 + tid + it * 256];
        }

        #pragma unroll
        for (int ks = 0; ks < 4; ks++) {
            const uint32_t swA = ((((uint32_t)ks << 1) | khA) ^ lx) << 4;
            const uint32_t swB = ((((uint32_t)ks << 1) | khB) ^ lx) << 4;
            uint32_t ah[2][4];
            ldsm4(ah[0], xb + arow_off + swA);
            ldsm4(ah[1], xb + arow_off + 4096 + swA);
            uint32_t bf[2][4];
            ldsm4(bf[0], preB + swB);
            ldsm4(bf[1], preB + 4096 + swB);
            #pragma unroll
            for (int np = 0; np < 2; np++) {
                #pragma unroll
                for (int mt = 0; mt < 2; mt++) {
                    mma_f16(acc[mt][2 * np],     ah[mt], bf[np][0], bf[np][1]);
                    mma_f16(acc[mt][2 * np + 1], ah[mt], bf[np][2], bf[np][3]);
                }
            }
        }

        if (more) {
            #pragma unroll
            for (int it = 0; it < 4; it++) cvt_sts_x(nxb, tid + it * 256, s[it]);
            #pragma unroll
            for (int it = 0; it < 4; it++) s[it] = xg4[nb4 + 1024 + tid + it * 256];
        }

        #pragma unroll
        for (int ks = 4; ks < 8; ks++) {
            const uint32_t swA = ((((uint32_t)ks << 1) | khA) ^ lx) << 4;
            const uint32_t swB = ((((uint32_t)ks << 1) | khB) ^ lx) << 4;
            uint32_t ah[2][4];
            ldsm4(ah[0], xb + arow_off + swA);
            ldsm4(ah[1], xb + arow_off + 4096 + swA);
            uint32_t bf[2][4];
            ldsm4(bf[0], preB + swB);
            ldsm4(bf[1], preB + 4096 + swB);
            #pragma unroll
            for (int np = 0; np < 2; np++) {
                #pragma unroll
                for (int mt = 0; mt < 2; mt++) {
                    mma_f16(acc[mt][2 * np],     ah[mt], bf[np][0], bf[np][1]);
                    mma_f16(acc[mt][2 * np + 1], ah[mt], bf[np][2], bf[np][3]);
                }
            }
        }

        if (more) {
            #pragma unroll
            for (int it = 0; it < 4; it++) cvt_sts_x(nxb, 1024 + tid + it * 256, s[it]);
        }

        // ---- per-warp staged epilogue (1KB buffer each, no CTA barrier) ----
        {
            const uint32_t ebuf = sb + SM_EPI + (uint32_t)wid * 1024;
            const uint32_t rl   = (uint32_t)(lane >> 2);             // 0..7
            const uint32_t sbase = ebuf + rl * 128 + ((uint32_t)(lane & 3) << 3);
            const uint32_t colq = (uint32_t)(lane & 7);              // 16B chunk
            const uint32_t ntr  = colq >> 1;
            const uint32_t rloc = (uint32_t)(lane >> 3);             // 0..3
            const size_t m0r = (size_t)mtile * TILE_M + (size_t)(wm * 32);
            const int    cb  = nh * 128 + wn * 32;

            #pragma unroll
            for (int g = 0; g < 4; g++) {
                const int mt = g >> 1;
                const int hf = g & 1;
                #pragma unroll
                for (int nt = 0; nt < 4; nt++) {
                    float z0 = acc[mt][nt][hf * 2 + 0] + bp[nt].x;
                    float z1 = acc[mt][nt][hf * 2 + 1] + bp[nt].y;
                    sts64(sbase + (((uint32_t)nt ^ (rl & 3)) << 5),
                          __float_as_uint(z0 * z0), __float_as_uint(z1 * z1));
                }
                __syncwarp();
                const size_t rowg0 = m0r + (size_t)(mt * 16 + hf * 8);
                #pragma unroll
                for (int p = 0; p < 2; p++) {
                    const uint32_t r = rloc + p * 4;
                    float v[4];
                    lds128(v, ebuf + r * 128 + ((ntr ^ (r & 3)) << 5) + ((colq & 1) << 4));
                    float4* dst = reinterpret_cast<float4*>(
                        out + (rowg0 + r) * ODIM + cb + colq * 4);
                    dst->x = v[0]; dst->y = v[1]; dst->z = v[2]; dst->w = v[3];
                }
                __syncwarp();
            }

            #pragma unroll
            for (int mt = 0; mt < 2; mt++)
                #pragma unroll
                for (int nt = 0; nt < 4; nt++)
                    #pragma unroll
                    for (int q = 0; q < 4; q++) acc[mt][nt][q] = 0.0f;
        }

        __syncthreads();   // nxb complete + xb free before next tile
    }
}

extern "C" void kernel_launch(void* const* d_in, const int* in_sizes, int n_in,
                              void* d_out, int out_size) {
    const float* x = (const float*)d_in[0];
    const float* w = (const float*)d_in[1];
    const float* b = (const float*)d_in[2];
    float* out = (float*)d_out;

    cudaFuncSetAttribute(hyper_kernel, cudaFuncAttributeMaxDynamicSharedMemorySize, SM_TOTAL);
    hyper_kernel<<<GRID, 256, SM_TOTAL>>>(x, w, b, out);
}

// round 11
// speedup vs baseline: 1.0005x; 1.0005x over previous
#include <cuda_runtime.h>
#include <cuda_fp16.h>
#include <cstdint>

// out[B,256] = (x[B,128] @ W[256,128]^T + bias)^2
// Single-term fp16 mma.sync GEMM, fp32 accum. rel_err ~3.5e-4 (calibrated).
// N split across CTAs: each CTA does a 64x128 tile, 3 CTAs/SM (6 warps/SMSP).

#define DDIM   128
#define ODIM   256
#define TILE_M 64
#define NITEMS 4096          // 2048 m-tiles x 2 n-halves
#define GRID   444           // 3 * 148
#define MSTEP  222           // GRID/2 m-tiles per step

// smem (bytes), per CTA
#define SM_W     0            // W half: 128 rows x 256B swizzled = 32768
#define SM_A0    32768        // A buf 0: 64x128 fp16 = 16384
#define SM_A1    49152        // A buf 1
#define SM_EPI   65536        // epilogue staging: 8 warps x 1KB
#define SM_TOTAL 73728

static __device__ __forceinline__ uint32_t smem_u32(const void* p) {
    uint32_t a;
    asm("{ .reg .u64 t; cvta.to.shared.u64 t, %1; cvt.u32.u64 %0, t; }" : "=r"(a) : "l"(p));
    return a;
}

static __device__ __forceinline__ void ldsm4(uint32_t* r, uint32_t a) {
    asm volatile("ldmatrix.sync.aligned.m8n8.x4.shared.b16 {%0,%1,%2,%3}, [%4];"
                 : "=r"(r[0]), "=r"(r[1]), "=r"(r[2]), "=r"(r[3]) : "r"(a));
}

static __device__ __forceinline__ void sts64(uint32_t a, uint32_t v0, uint32_t v1) {
    asm volatile("st.shared.v2.b32 [%0], {%1, %2};" :: "r"(a), "r"(v0), "r"(v1));
}

static __device__ __forceinline__ void lds128(float* v, uint32_t a) {
    asm volatile("ld.shared.v4.f32 {%0,%1,%2,%3}, [%4];"
                 : "=f"(v[0]), "=f"(v[1]), "=f"(v[2]), "=f"(v[3]) : "r"(a));
}

static __device__ __forceinline__ void mma_f16(float* d, const uint32_t* a,
                                               uint32_t b0, uint32_t b1) {
    asm volatile(
        "mma.sync.aligned.m16n8k16.row.col.f32.f16.f16.f32 "
        "{%0,%1,%2,%3}, {%4,%5,%6,%7}, {%8,%9}, {%0,%1,%2,%3};"
        : "+f"(d[0]), "+f"(d[1]), "+f"(d[2]), "+f"(d[3])
        : "r"(a[0]), "r"(a[1]), "r"(a[2]), "r"(a[3]), "r"(b0), "r"(b1));
}

// convert one staged float4 (flat float4-index of a 64x128 tile) into A buffer
static __device__ __forceinline__ void cvt_sts_x(uint32_t xb, int idx4, float4 v) {
    const int row = idx4 >> 5;          // 0..63
    const int cg  = idx4 & 31;
    uint32_t h0, h1;
    asm("cvt.rn.f16x2.f32 %0, %1, %2;" : "=r"(h0) : "f"(v.y), "f"(v.x));
    asm("cvt.rn.f16x2.f32 %0, %1, %2;" : "=r"(h1) : "f"(v.w), "f"(v.z));
    const uint32_t a = xb + (uint32_t)row * 256 +
                       ((uint32_t)(((cg >> 1) ^ (row & 7)) << 4)) + ((cg & 1) << 3);
    sts64(a, h0, h1);
}

__global__ void __launch_bounds__(256, 3)
hyper_kernel(const float* __restrict__ xg, const float* __restrict__ wg,
             const float* __restrict__ bg, float* __restrict__ out) {
    extern __shared__ __align__(16) char smem[];
    const uint32_t sb = smem_u32(smem);
    const int tid  = threadIdx.x;
    const int lane = tid & 31;
    const int wid  = tid >> 5;
    const int wm   = wid >> 2;           // 0..1 : rows wm*32 .. +31
    const int wn   = wid & 3;            // 0..3 : cols wn*32 .. +31 (within n-half)
    const int bid  = blockIdx.x;
    const int nh   = bid & 1;            // n-half: fixed per CTA (GRID even)

    const float4* xg4 = reinterpret_cast<const float4*>(xg);

    // prefetch tile 0 (overlaps W init)
    const int mt0 = bid >> 1;
    float4 st0[8];
    {
        const size_t b4 = (size_t)mt0 * (TILE_M * 32);
        #pragma unroll
        for (int it = 0; it < 8; it++) st0[it] = xg4[b4 + tid + it * 256];
    }

    // W half (rows nh*128 .. +127): fp32 -> fp16, swizzled 256B rows
    {
        const float4* w4 = reinterpret_cast<const float4*>(wg) + (size_t)nh * 128 * 32;
        #pragma unroll 4
        for (int i = tid; i < 128 * 32; i += 256) {
            const int n  = i >> 5;
            const int cg = i & 31;
            float4 v = w4[i];
            uint32_t p0, p1;
            asm("cvt.rn.f16x2.f32 %0, %1, %2;" : "=r"(p0) : "f"(v.y), "f"(v.x));
            asm("cvt.rn.f16x2.f32 %0, %1, %2;" : "=r"(p1) : "f"(v.w), "f"(v.z));
            const uint32_t a = sb + SM_W + (uint32_t)n * 256 +
                               ((uint32_t)(((cg >> 1) ^ (n & 7)) << 4)) + ((cg & 1) << 3);
            sts64(a, p0, p1);
        }
    }

    // tile 0 -> A buffer 0
    #pragma unroll
    for (int it = 0; it < 8; it++) cvt_sts_x(sb + SM_A0, tid + it * 256, st0[it]);
    __syncthreads();

    float acc[2][4][4];
    #pragma unroll
    for (int mt = 0; mt < 2; mt++)
        #pragma unroll
        for (int nt = 0; nt < 4; nt++)
            #pragma unroll
            for (int q = 0; q < 4; q++) acc[mt][nt][q] = 0.0f;

    // bias pairs (constant across tiles) straight from global (tiny, L2)
    float2 bp[4];
    #pragma unroll
    for (int nt = 0; nt < 4; nt++)
        bp[nt] = *reinterpret_cast<const float2*>(
            bg + nh * 128 + wn * 32 + nt * 8 + (lane & 3) * 2);

    const uint32_t lx  = (uint32_t)(lane & 7);
    const uint32_t khA = (uint32_t)((lane >> 4) & 1);
    const uint32_t khB = (uint32_t)((lane >> 3) & 1);
    const uint32_t arow_off =
        (uint32_t)(wm * 32 + (lane & 7) + ((lane & 8) ? 8 : 0)) * 256;
    const uint32_t preB = sb + SM_W +
        (uint32_t)(wn * 32 + (lane & 7) + ((lane & 16) ? 8 : 0)) * 256;
    const int my_n = (NITEMS - bid + GRID - 1) / GRID;

    for (int tt = 0; tt < my_n; tt++) {
        const int mtile = mt0 + tt * MSTEP;
        const uint32_t xb  = sb + ((tt & 1) ? SM_A1 : SM_A0);
        const uint32_t nxb = sb + ((tt & 1) ? SM_A0 : SM_A1);
        const bool more = (tt + 1 < my_n);
        const size_t nb4 = more ? ((size_t)(mtile + MSTEP) * (TILE_M * 32)) : 0;

        float4 s[4];
        if (more) {
            #pragma unroll
            for (int it = 0; it < 4; it++) s[it] = xg4[nb4 + tid + it * 256];
        }

        #pragma unroll
        for (int ks = 0; ks < 4; ks++) {
            const uint32_t swA = ((((uint32_t)ks << 1) | khA) ^ lx) << 4;
            const uint32_t swB = ((((uint32_t)ks << 1) | khB) ^ lx) << 4;
            uint32_t ah[2][4];
            ldsm4(ah[0], xb + arow_off + swA);
            ldsm4(ah[1], xb + arow_off + 4096 + swA);
            uint32_t bf[2][4];
            ldsm4(bf[0], preB + swB);
            ldsm4(bf[1], preB + 4096 + swB);
            #pragma unroll
            for (int np = 0; np < 2; np++) {
                #pragma unroll
                for (int mt = 0; mt < 2; mt++) {
                    mma_f16(acc[mt][2 * np],     ah[mt], bf[np][0], bf[np][1]);
                    mma_f16(acc[mt][2 * np + 1], ah[mt], bf[np][2], bf[np][3]);
                }
            }
        }

        if (more) {
            #pragma unroll
            for (int it = 0; it < 4; it++) cvt_sts_x(nxb, tid + it * 256, s[it]);
            #pragma unroll
            for (int it = 0; it < 4; it++) s[it] = xg4[nb4 + 1024 + tid + it * 256];
        }

        #pragma unroll
        for (int ks = 4; ks < 8; ks++) {
            const uint32_t swA = ((((uint32_t)ks << 1) | khA) ^ lx) << 4;
            const uint32_t swB = ((((uint32_t)ks << 1) | khB) ^ lx) << 4;
            uint32_t ah[2][4];
            ldsm4(ah[0], xb + arow_off + swA);
            ldsm4(ah[1], xb + arow_off + 4096 + swA);
            uint32_t bf[2][4];
            ldsm4(bf[0], preB + swB);
            ldsm4(bf[1], preB + 4096 + swB);
            #pragma unroll
            for (int np = 0; np < 2; np++) {
                #pragma unroll
                for (int mt = 0; mt < 2; mt++) {
                    mma_f16(acc[mt][2 * np],     ah[mt], bf[np][0], bf[np][1]);
                    mma_f16(acc[mt][2 * np + 1], ah[mt], bf[np][2], bf[np][3]);
                }
            }
        }

        if (more) {
            #pragma unroll
            for (int it = 0; it < 4; it++) cvt_sts_x(nxb, 1024 + tid + it * 256, s[it]);
        }

        // ---- per-warp staged epilogue (1KB buffer each, no CTA barrier) ----
        {
            const uint32_t ebuf = sb + SM_EPI + (uint32_t)wid * 1024;
            const uint32_t rl   = (uint32_t)(lane >> 2);             // 0..7
            const uint32_t sbase = ebuf + rl * 128 + ((uint32_t)(lane & 3) << 3);
            const uint32_t colq = (uint32_t)(lane & 7);              // 16B chunk
            const uint32_t ntr  = colq >> 1;
            const uint32_t rloc = (uint32_t)(lane >> 3);             // 0..3
            const size_t m0r = (size_t)mtile * TILE_M + (size_t)(wm * 32);
            const int    cb  = nh * 128 + wn * 32;

            #pragma unroll
            for (int g = 0; g < 4; g++) {
                const int mt = g >> 1;
                const int hf = g & 1;
                #pragma unroll
                for (int nt = 0; nt < 4; nt++) {
                    float z0 = acc[mt][nt][hf * 2 + 0] + bp[nt].x;
                    float z1 = acc[mt][nt][hf * 2 + 1] + bp[nt].y;
                    sts64(sbase + (((uint32_t)nt ^ (rl & 3)) << 5),
                          __float_as_uint(z0 * z0), __float_as_uint(z1 * z1));
                }
                __syncwarp();
                const size_t rowg0 = m0r + (size_t)(mt * 16 + hf * 8);
                #pragma unroll
                for (int p = 0; p < 2; p++) {
                    const uint32_t r = rloc + p * 4;
                    float v[4];
                    lds128(v, ebuf + r * 128 + ((ntr ^ (r & 3)) << 5) + ((colq & 1) << 4));
                    float4* dst = reinterpret_cast<float4*>(
                        out + (rowg0 + r) * ODIM + cb + colq * 4);
                    dst->x = v[0]; dst->y = v[1]; dst->z = v[2]; dst->w = v[3];
                }
                __syncwarp();
            }

            #pragma unroll
            for (int mt = 0; mt < 2; mt++)
                #pragma unroll
                for (int nt = 0; nt < 4; nt++)
                    #pragma unroll
                    for (int q = 0; q < 4; q++) acc[mt][nt][q] = 0.0f;
        }

        __syncthreads();   // nxb complete + xb free before next tile
    }
}

extern "C" void kernel_launch(void* const* d_in, const int* in_sizes, int n_in,
                              void* d_out, int out_size) {
    const float* x = (const float*)d_in[0];
    const float* w = (const float*)d_in[1];
    const float* b = (const float*)d_in[2];
    float* out = (float*)d_out;

    cudaFuncSetAttribute(hyper_kernel, cudaFuncAttributeMaxDynamicSharedMemorySize, SM_TOTAL);
    hyper_kernel<<<GRID, 256, SM_TOTAL>>>(x, w, b, out);
}

// round 15
// speedup vs baseline: 1.0726x; 1.0720x over previous
#include <cuda_runtime.h>
#include <cuda_fp16.h>
#include <cstdint>

// out[B,256] = (x[B,128] @ W[256,128]^T + bias)^2
// Single-term fp16 mma.sync GEMM, fp32 accum. rel_err ~3.5e-4 (calibrated).
// R7 structure (2 CTAs/SM, staged epilogue) + software-pipelined k-loop:
// rolling B-frag pairs between MMA quads, A-frag prefetch for ks+1.

#define DDIM   128
#define ODIM   256
#define TILE_M 64
#define NTILES 2048
#define GRID   296

// smem (bytes), per CTA
#define SM_W     0            // W fp16 [256][128] swizzled, 65536
#define SM_A0    65536        // A buf 0: 64x128 fp16, 16384
#define SM_A1    81920        // A buf 1
#define SM_EPI   98304        // epilogue staging, 8 warps x 2KB
#define SM_BIAS  114688
#define SM_TOTAL 115712

static __device__ __forceinline__ uint32_t smem_u32(const void* p) {
    uint32_t a;
    asm("{ .reg .u64 t; cvta.to.shared.u64 t, %1; cvt.u32.u64 %0, t; }" : "=r"(a) : "l"(p));
    return a;
}

static __device__ __forceinline__ void ldsm4(uint32_t* r, uint32_t a) {
    asm volatile("ldmatrix.sync.aligned.m8n8.x4.shared.b16 {%0,%1,%2,%3}, [%4];"
                 : "=r"(r[0]), "=r"(r[1]), "=r"(r[2]), "=r"(r[3]) : "r"(a));
}

static __device__ __forceinline__ void sts64(uint32_t a, uint32_t v0, uint32_t v1) {
    asm volatile("st.shared.v2.b32 [%0], {%1, %2};" :: "r"(a), "r"(v0), "r"(v1));
}

static __device__ __forceinline__ void lds128(float* v, uint32_t a) {
    asm volatile("ld.shared.v4.f32 {%0,%1,%2,%3}, [%4];"
                 : "=f"(v[0]), "=f"(v[1]), "=f"(v[2]), "=f"(v[3]) : "r"(a));
}

static __device__ __forceinline__ void mma_f16(float* d, const uint32_t* a,
                                               uint32_t b0, uint32_t b1) {
    asm volatile(
        "mma.sync.aligned.m16n8k16.row.col.f32.f16.f16.f32 "
        "{%0,%1,%2,%3}, {%4,%5,%6,%7}, {%8,%9}, {%0,%1,%2,%3};"
        : "+f"(d[0]), "+f"(d[1]), "+f"(d[2]), "+f"(d[3])
        : "r"(a[0]), "r"(a[1]), "r"(a[2]), "r"(a[3]), "r"(b0), "r"(b1));
}

// convert one staged float4 (flat float4-index of a 64x128 tile) into A buffer
static __device__ __forceinline__ void cvt_sts_x(uint32_t xb, int idx4, float4 v) {
    const int row = idx4 >> 5;          // 0..63
    const int cg  = idx4 & 31;
    uint32_t h0, h1;
    asm("cvt.rn.f16x2.f32 %0, %1, %2;" : "=r"(h0) : "f"(v.y), "f"(v.x));
    asm("cvt.rn.f16x2.f32 %0, %1, %2;" : "=r"(h1) : "f"(v.w), "f"(v.z));
    const uint32_t a = xb + (uint32_t)row * 256 +
                       ((uint32_t)(((cg >> 1) ^ (row & 7)) << 4)) + ((cg & 1) << 3);
    sts64(a, h0, h1);
}

__global__ void __launch_bounds__(256, 2)
hyper_kernel(const float* __restrict__ xg, const float* __restrict__ wg,
             const float* __restrict__ bg, float* __restrict__ out) {
    extern __shared__ __align__(16) char smem[];
    const uint32_t sb = smem_u32(smem);
    const int tid  = threadIdx.x;
    const int lane = tid & 31;
    const int wid  = tid >> 5;
    const int wm   = wid >> 2;           // 0..1 : rows wm*32 .. +31
    const int wn   = wid & 3;            // 0..3 : cols wn*64 .. +63
    const int bid  = blockIdx.x;

    // bias -> smem
    reinterpret_cast<float*>(smem + SM_BIAS)[tid] = bg[tid];

    const float4* xg4 = reinterpret_cast<const float4*>(xg);

    // prefetch tile 0 (overlaps W init)
    float4 st0[8];
    {
        const size_t b4 = (size_t)bid * (TILE_M * 32);
        #pragma unroll
        for (int it = 0; it < 8; it++) st0[it] = xg4[b4 + tid + it * 256];
    }

    // W: fp32 -> fp16, swizzled smem [n][k], 256B rows (persistent)
    {
        const float4* w4 = reinterpret_cast<const float4*>(wg);
        #pragma unroll 4
        for (int i = tid; i < ODIM * 32; i += 256) {
            const int n  = i >> 5;
            const int cg = i & 31;
            float4 v = w4[i];
            uint32_t p0, p1;
            asm("cvt.rn.f16x2.f32 %0, %1, %2;" : "=r"(p0) : "f"(v.y), "f"(v.x));
            asm("cvt.rn.f16x2.f32 %0, %1, %2;" : "=r"(p1) : "f"(v.w), "f"(v.z));
            const uint32_t a = sb + SM_W + (uint32_t)n * 256 +
                               ((uint32_t)(((cg >> 1) ^ (n & 7)) << 4)) + ((cg & 1) << 3);
            sts64(a, p0, p1);
        }
    }

    // tile 0 -> A buffer 0
    #pragma unroll
    for (int it = 0; it < 8; it++) cvt_sts_x(sb + SM_A0, tid + it * 256, st0[it]);
    __syncthreads();

    float acc[2][8][4];
    #pragma unroll
    for (int mt = 0; mt < 2; mt++)
        #pragma unroll
        for (int nt = 0; nt < 8; nt++)
            #pragma unroll
            for (int q = 0; q < 4; q++) acc[mt][nt][q] = 0.0f;

    const uint32_t lx  = (uint32_t)(lane & 7);
    const uint32_t khA = (uint32_t)((lane >> 4) & 1);
    const uint32_t khB = (uint32_t)((lane >> 3) & 1);
    const uint32_t arow_off =
        (uint32_t)(wm * 32 + (lane & 7) + ((lane & 8) ? 8 : 0)) * 256;
    const uint32_t preB = sb + SM_W +
        (uint32_t)(wn * 64 + (lane & 7) + ((lane & 16) ? 8 : 0)) * 256;
    const float* bs = reinterpret_cast<const float*>(smem + SM_BIAS);
    const int my_n = (NTILES - bid + GRID - 1) / GRID;

    for (int tt = 0; tt < my_n; tt++) {
        const int tile = bid + tt * GRID;
        const uint32_t xb  = sb + ((tt & 1) ? SM_A1 : SM_A0);
        const uint32_t nxb = sb + ((tt & 1) ? SM_A0 : SM_A1);
        const bool more = (tt + 1 < my_n);
        const size_t nb4 = more ? ((size_t)(tile + GRID) * (TILE_M * 32)) : 0;

        float4 s0[4], s1[4];

        // LDG s0
        if (more) {
            #pragma unroll
            for (int it = 0; it < 4; it++) s0[it] = xg4[nb4 + tid + it * 256];
        }

        // ---- software-pipelined k-loop ----
        uint32_t ah[2][2][4];   // [ks parity][mt][4]
        {
            const uint32_t swA0 = (khA ^ lx) << 4;     // ks = 0
            ldsm4(ah[0][0], xb + arow_off + swA0);
            ldsm4(ah[0][1], xb + arow_off + 4096 + swA0);
        }

        #pragma unroll
        for (int ks = 0; ks < 8; ks++) {
            const int par = ks & 1;
            const uint32_t swB  = ((((uint32_t)ks << 1) | khB) ^ lx) << 4;
            const uint32_t swAn = ((((uint32_t)(ks + 1) << 1) | khA) ^ lx) << 4;
            uint32_t b0[4], b1[4];

            ldsm4(b0, preB + swB);                         // np0
            ldsm4(b1, preB + 4096 + swB);                  // np1
            #pragma unroll
            for (int mt = 0; mt < 2; mt++) {               // mma np0
                mma_f16(acc[mt][0], ah[par][mt], b0[0], b0[1]);
                mma_f16(acc[mt][1], ah[par][mt], b0[2], b0[3]);
            }
            ldsm4(b0, preB + 8192 + swB);                  // np2
            #pragma unroll
            for (int mt = 0; mt < 2; mt++) {               // mma np1
                mma_f16(acc[mt][2], ah[par][mt], b1[0], b1[1]);
                mma_f16(acc[mt][3], ah[par][mt], b1[2], b1[3]);
            }
            ldsm4(b1, preB + 12288 + swB);                 // np3
            #pragma unroll
            for (int mt = 0; mt < 2; mt++) {               // mma np2
                mma_f16(acc[mt][4], ah[par][mt], b0[0], b0[1]);
                mma_f16(acc[mt][5], ah[par][mt], b0[2], b0[3]);
            }
            if (ks < 7) {                                  // prefetch A for ks+1
                ldsm4(ah[par ^ 1][0], xb + arow_off + swAn);
                ldsm4(ah[par ^ 1][1], xb + arow_off + 4096 + swAn);
            }
            #pragma unroll
            for (int mt = 0; mt < 2; mt++) {               // mma np3
                mma_f16(acc[mt][6], ah[par][mt], b1[0], b1[1]);
                mma_f16(acc[mt][7], ah[par][mt], b1[2], b1[3]);
            }

            // x feed for next tile, spread at fixed ks points (same as R7)
            if (ks == 3 && more) {
                #pragma unroll
                for (int it = 0; it < 4; it++) cvt_sts_x(nxb, tid + it * 256, s0[it]);
                #pragma unroll
                for (int it = 0; it < 4; it++) s1[it] = xg4[nb4 + 1024 + tid + it * 256];
            }
        }

        if (more) {
            #pragma unroll
            for (int it = 0; it < 4; it++) cvt_sts_x(nxb, 1024 + tid + it * 256, s1[it]);
        }

        // ---- per-warp staged epilogue (own buffer, no CTA barrier needed) ----
        {
            float2 bp[8];
            #pragma unroll
            for (int nt = 0; nt < 8; nt++)
                bp[nt] = *reinterpret_cast<const float2*>(
                    bs + wn * 64 + nt * 8 + (lane & 3) * 2);

            const uint32_t ebuf = sb + SM_EPI + (uint32_t)wid * 2048;
            const uint32_t rl   = (uint32_t)(lane >> 2);          // 0..7
            const uint32_t sbase = ebuf + rl * 256 + ((uint32_t)(lane & 3) << 3);
            const size_t  m0 = (size_t)tile * TILE_M;
            const uint32_t c  = (uint32_t)(lane & 15);
            const uint32_t rref = (uint32_t)(lane >> 4);          // 0..1

            #pragma unroll
            for (int g = 0; g < 4; g++) {
                const int mt = g >> 1;
                const int hf = g & 1;
                #pragma unroll
                for (int nt = 0; nt < 8; nt++) {
                    float z0 = acc[mt][nt][hf * 2 + 0] + bp[nt].x;
                    float z1 = acc[mt][nt][hf * 2 + 1] + bp[nt].y;
                    sts64(sbase + (((uint32_t)nt ^ rl) << 5),
                          __float_as_uint(z0 * z0), __float_as_uint(z1 * z1));
                }
                __syncwarp();
                const size_t rowg0 = m0 + (size_t)(wm * 32 + mt * 16 + hf * 8);
                #pragma unroll
                for (int j = 0; j < 4; j++) {
                    const uint32_t r = 2 * j + rref;
                    float v[4];
                    lds128(v, ebuf + r * 256 + ((((c >> 1) ^ r) << 5)) + ((c & 1) << 4));
                    float4* dst = reinterpret_cast<float4*>(
                        out + (rowg0 + r) * ODIM + wn * 64 + c * 4);
                    dst->x = v[0]; dst->y = v[1]; dst->z = v[2]; dst->w = v[3];
                }
                __syncwarp();
            }

            #pragma unroll
            for (int mt = 0; mt < 2; mt++)
                #pragma unroll
                for (int nt = 0; nt < 8; nt++)
                    #pragma unroll
                    for (int q = 0; q < 4; q++) acc[mt][nt][q] = 0.0f;
        }

        __syncthreads();   // nxb complete + xb free before next tile
    }
}

extern "C" void kernel_launch(void* const* d_in, const int* in_sizes, int n_in,
                              void* d_out, int out_size) {
    const float* x = (const float*)d_in[0];
    const float* w = (const float*)d_in[1];
    const float* b = (const float*)d_in[2];
    float* out = (float*)d_out;

    cudaFuncSetAttribute(hyper_kernel, cudaFuncAttributeMaxDynamicSharedMemorySize, SM_TOTAL);
    hyper_kernel<<<GRID, 256, SM_TOTAL>>>(x, w, b, out);
}

// round 16
// speedup vs baseline: 1.2238x; 1.1410x over previous
#include <cuda_runtime.h>
#include <cuda_fp16.h>
#include <cstdint>

// out[B,256] = (x[B,128] @ W[256,128]^T + bias)^2
// Single-term fp16 mma.sync GEMM, fp32 accum. rel_err ~3.5e-4 (calibrated).
// TILE_M=128, warp grid 2m x 4n, acc=128 regs, occ 1: -33% fragment traffic.
// B in smem; R7 burst k-loop; per-warp staged epilogue; 1 barrier/tile.

#define DDIM   128
#define ODIM   256
#define TILE_M 128
#define NTILES 1024
#define GRID   148

// smem (bytes), per CTA
#define SM_W     0            // W fp16 [256][128] swizzled, 65536
#define SM_A0    65536        // A buf 0: 128x128 fp16, 32768
#define SM_A1    98304        // A buf 1
#define SM_EPI   131072       // epilogue staging, 8 warps x 2KB
#define SM_BIAS  147456
#define SM_TOTAL 148480

static __device__ __forceinline__ uint32_t smem_u32(const void* p) {
    uint32_t a;
    asm("{ .reg .u64 t; cvta.to.shared.u64 t, %1; cvt.u32.u64 %0, t; }" : "=r"(a) : "l"(p));
    return a;
}

static __device__ __forceinline__ void ldsm4(uint32_t* r, uint32_t a) {
    asm volatile("ldmatrix.sync.aligned.m8n8.x4.shared.b16 {%0,%1,%2,%3}, [%4];"
                 : "=r"(r[0]), "=r"(r[1]), "=r"(r[2]), "=r"(r[3]) : "r"(a));
}

static __device__ __forceinline__ void sts64(uint32_t a, uint32_t v0, uint32_t v1) {
    asm volatile("st.shared.v2.b32 [%0], {%1, %2};" :: "r"(a), "r"(v0), "r"(v1));
}

static __device__ __forceinline__ void lds128(float* v, uint32_t a) {
    asm volatile("ld.shared.v4.f32 {%0,%1,%2,%3}, [%4];"
                 : "=f"(v[0]), "=f"(v[1]), "=f"(v[2]), "=f"(v[3]) : "r"(a));
}

static __device__ __forceinline__ void mma_f16(float* d, const uint32_t* a,
                                               uint32_t b0, uint32_t b1) {
    asm volatile(
        "mma.sync.aligned.m16n8k16.row.col.f32.f16.f16.f32 "
        "{%0,%1,%2,%3}, {%4,%5,%6,%7}, {%8,%9}, {%0,%1,%2,%3};"
        : "+f"(d[0]), "+f"(d[1]), "+f"(d[2]), "+f"(d[3])
        : "r"(a[0]), "r"(a[1]), "r"(a[2]), "r"(a[3]), "r"(b0), "r"(b1));
}

// convert one staged float4 (flat float4-index of a 128x128 tile) into A buffer
static __device__ __forceinline__ void cvt_sts_x(uint32_t xb, int idx4, float4 v) {
    const int row = idx4 >> 5;          // 0..127
    const int cg  = idx4 & 31;
    uint32_t h0, h1;
    asm("cvt.rn.f16x2.f32 %0, %1, %2;" : "=r"(h0) : "f"(v.y), "f"(v.x));
    asm("cvt.rn.f16x2.f32 %0, %1, %2;" : "=r"(h1) : "f"(v.w), "f"(v.z));
    const uint32_t a = xb + (uint32_t)row * 256 +
                       ((uint32_t)(((cg >> 1) ^ (row & 7)) << 4)) + ((cg & 1) << 3);
    sts64(a, h0, h1);
}

__global__ void __launch_bounds__(256, 1)
hyper_kernel(const float* __restrict__ xg, const float* __restrict__ wg,
             const float* __restrict__ bg, float* __restrict__ out) {
    extern __shared__ __align__(16) char smem[];
    const uint32_t sb = smem_u32(smem);
    const int tid  = threadIdx.x;
    const int lane = tid & 31;
    const int wid  = tid >> 5;
    const int wm   = wid >> 2;           // 0..1 : rows wm*64 .. +63
    const int wn   = wid & 3;            // 0..3 : cols wn*64 .. +63
    const int bid  = blockIdx.x;

    // bias -> smem
    reinterpret_cast<float*>(smem + SM_BIAS)[tid] = bg[tid];

    const float4* xg4 = reinterpret_cast<const float4*>(xg);

    // prefetch tile 0 (overlaps W init): 128x128 fp32 = 4096 float4
    float4 st0[8];
    {
        const size_t b4 = (size_t)bid * (TILE_M * 32);
        #pragma unroll
        for (int it = 0; it < 8; it++) st0[it] = xg4[b4 + tid + it * 256];
    }

    // W: fp32 -> fp16, swizzled smem [n][k], 256B rows (persistent)
    {
        const float4* w4 = reinterpret_cast<const float4*>(wg);
        #pragma unroll 4
        for (int i = tid; i < ODIM * 32; i += 256) {
            const int n  = i >> 5;
            const int cg = i & 31;
            float4 v = w4[i];
            uint32_t p0, p1;
            asm("cvt.rn.f16x2.f32 %0, %1, %2;" : "=r"(p0) : "f"(v.y), "f"(v.x));
            asm("cvt.rn.f16x2.f32 %0, %1, %2;" : "=r"(p1) : "f"(v.w), "f"(v.z));
            const uint32_t a = sb + SM_W + (uint32_t)n * 256 +
                               ((uint32_t)(((cg >> 1) ^ (n & 7)) << 4)) + ((cg & 1) << 3);
            sts64(a, p0, p1);
        }
    }

    // tile 0 first half -> A buffer 0; second half loaded then stored
    #pragma unroll
    for (int it = 0; it < 8; it++) cvt_sts_x(sb + SM_A0, tid + it * 256, st0[it]);
    {
        const size_t b4 = (size_t)bid * (TILE_M * 32);
        #pragma unroll
        for (int it = 8; it < 16; it++) {
            float4 v = xg4[b4 + tid + it * 256];
            cvt_sts_x(sb + SM_A0, tid + it * 256, v);
        }
    }
    __syncthreads();

    float acc[4][8][4];
    #pragma unroll
    for (int mt = 0; mt < 4; mt++)
        #pragma unroll
        for (int nt = 0; nt < 8; nt++)
            #pragma unroll
            for (int q = 0; q < 4; q++) acc[mt][nt][q] = 0.0f;

    const uint32_t lx  = (uint32_t)(lane & 7);
    const uint32_t khA = (uint32_t)((lane >> 4) & 1);
    const uint32_t khB = (uint32_t)((lane >> 3) & 1);
    const uint32_t arow_off =
        (uint32_t)(wm * 64 + (lane & 7) + ((lane & 8) ? 8 : 0)) * 256;
    const uint32_t preB = sb + SM_W +
        (uint32_t)(wn * 64 + (lane & 7) + ((lane & 16) ? 8 : 0)) * 256;
    const float* bs = reinterpret_cast<const float*>(smem + SM_BIAS);
    const int my_n = (NTILES - bid + GRID - 1) / GRID;

    for (int tt = 0; tt < my_n; tt++) {
        const int tile = bid + tt * GRID;
        const uint32_t xb  = sb + ((tt & 1) ? SM_A1 : SM_A0);
        const uint32_t nxb = sb + ((tt & 1) ? SM_A0 : SM_A1);
        const bool more = (tt + 1 < my_n);
        const size_t nb4 = more ? ((size_t)(tile + GRID) * (TILE_M * 32)) : 0;

        float4 s0[8];

        // LDG first half of next tile
        if (more) {
            #pragma unroll
            for (int it = 0; it < 8; it++) s0[it] = xg4[nb4 + tid + it * 256];
        }

        #pragma unroll
        for (int ks = 0; ks < 4; ks++) {
            const uint32_t swA = ((((uint32_t)ks << 1) | khA) ^ lx) << 4;
            const uint32_t swB = ((((uint32_t)ks << 1) | khB) ^ lx) << 4;
            uint32_t ah[4][4];
            #pragma unroll
            for (int mt = 0; mt < 4; mt++)
                ldsm4(ah[mt], xb + arow_off + ((uint32_t)mt << 12) + swA);
            uint32_t bf[4][4];
            #pragma unroll
            for (int np = 0; np < 4; np++)
                ldsm4(bf[np], preB + ((uint32_t)np << 12) + swB);
            #pragma unroll
            for (int np = 0; np < 4; np++) {
                #pragma unroll
                for (int mt = 0; mt < 4; mt++) {
                    mma_f16(acc[mt][2 * np],     ah[mt], bf[np][0], bf[np][1]);
                    mma_f16(acc[mt][2 * np + 1], ah[mt], bf[np][2], bf[np][3]);
                }
            }
        }

        // cvt+STS first half; LDG second half
        if (more) {
            #pragma unroll
            for (int it = 0; it < 8; it++) cvt_sts_x(nxb, tid + it * 256, s0[it]);
            #pragma unroll
            for (int it = 0; it < 8; it++) s0[it] = xg4[nb4 + 2048 + tid + it * 256];
        }

        #pragma unroll
        for (int ks = 4; ks < 8; ks++) {
            const uint32_t swA = ((((uint32_t)ks << 1) | khA) ^ lx) << 4;
            const uint32_t swB = ((((uint32_t)ks << 1) | khB) ^ lx) << 4;
            uint32_t ah[4][4];
            #pragma unroll
            for (int mt = 0; mt < 4; mt++)
                ldsm4(ah[mt], xb + arow_off + ((uint32_t)mt << 12) + swA);
            uint32_t bf[4][4];
            #pragma unroll
            for (int np = 0; np < 4; np++)
                ldsm4(bf[np], preB + ((uint32_t)np << 12) + swB);
            #pragma unroll
            for (int np = 0; np < 4; np++) {
                #pragma unroll
                for (int mt = 0; mt < 4; mt++) {
                    mma_f16(acc[mt][2 * np],     ah[mt], bf[np][0], bf[np][1]);
                    mma_f16(acc[mt][2 * np + 1], ah[mt], bf[np][2], bf[np][3]);
                }
            }
        }

        // cvt+STS second half
        if (more) {
            #pragma unroll
            for (int it = 0; it < 8; it++) cvt_sts_x(nxb, 2048 + tid + it * 256, s0[it]);
        }

        // ---- per-warp staged epilogue (own 2KB buffer, no CTA barrier) ----
        {
            float2 bp[8];
            #pragma unroll
            for (int nt = 0; nt < 8; nt++)
                bp[nt] = *reinterpret_cast<const float2*>(
                    bs + wn * 64 + nt * 8 + (lane & 3) * 2);

            const uint32_t ebuf = sb + SM_EPI + (uint32_t)wid * 2048;
            const uint32_t rl   = (uint32_t)(lane >> 2);          // 0..7
            const uint32_t sbase = ebuf + rl * 256 + ((uint32_t)(lane & 3) << 3);
            const size_t  m0 = (size_t)tile * TILE_M + (size_t)(wm * 64);
            const uint32_t c  = (uint32_t)(lane & 15);
            const uint32_t rref = (uint32_t)(lane >> 4);          // 0..1

            #pragma unroll
            for (int g = 0; g < 8; g++) {
                const int mt = g >> 1;
                const int hf = g & 1;
                #pragma unroll
                for (int nt = 0; nt < 8; nt++) {
                    float z0 = acc[mt][nt][hf * 2 + 0] + bp[nt].x;
                    float z1 = acc[mt][nt][hf * 2 + 1] + bp[nt].y;
                    sts64(sbase + (((uint32_t)nt ^ rl) << 5),
                          __float_as_uint(z0 * z0), __float_as_uint(z1 * z1));
                }
                __syncwarp();
                const size_t rowg0 = m0 + (size_t)(mt * 16 + hf * 8);
                #pragma unroll
                for (int j = 0; j < 4; j++) {
                    const uint32_t r = 2 * j + rref;
                    float v[4];
                    lds128(v, ebuf + r * 256 + ((((c >> 1) ^ r) << 5)) + ((c & 1) << 4));
                    float4* dst = reinterpret_cast<float4*>(
                        out + (rowg0 + r) * ODIM + wn * 64 + c * 4);
                    dst->x = v[0]; dst->y = v[1]; dst->z = v[2]; dst->w = v[3];
                }
                __syncwarp();
            }

            #pragma unroll
            for (int mt = 0; mt < 4; mt++)
                #pragma unroll
                for (int nt = 0; nt < 8; nt++)
                    #pragma unroll
                    for (int q = 0; q < 4; q++) acc[mt][nt][q] = 0.0f;
        }

        __syncthreads();   // nxb complete + xb free before next tile
    }
}

extern "C" void kernel_launch(void* const* d_in, const int* in_sizes, int n_in,
                              void* d_out, int out_size) {
    const float* x = (const float*)d_in[0];
    const float* w = (const float*)d_in[1];
    const float* b = (const float*)d_in[2];
    float* out = (float*)d_out;

    cudaFuncSetAttribute(hyper_kernel, cudaFuncAttributeMaxDynamicSharedMemorySize, SM_TOTAL);
    hyper_kernel<<<GRID, 256, SM_TOTAL>>>(x, w, b, out);
}